// round 8
// baseline (speedup 1.0000x reference)
#include <cuda_runtime.h>
#include <cuda_bf16.h>
#include <math.h>

// Shapes fixed by the reference
constexpr int Bc = 64;
constexpr int Tc = 2048;
constexpr int Vc = 256;
constexpr int Uc = 256;
#define NEGV (-1e30f)

constexpr int CHUNK = 8;   // timesteps per cp.async group (8 KB)
constexpr int NCH = 4;     // ring chunks
constexpr int PREF = 3;    // chunks in flight

__device__ float g_partial[Bc];

#define CP_ASYNC_16(dst, src)                                              \
    asm volatile("cp.async.cg.shared.global [%0], [%1], 16;\n" ::          \
                     "r"(dst), "l"(src))
#define CP_COMMIT() asm volatile("cp.async.commit_group;\n" ::: "memory")
#define CP_WAIT(n) asm volatile("cp.async.wait_group %0;\n" ::"n"(n) : "memory")

// Dynamic shared memory layout (bytes):
//   ring    [NCH*CHUNK][Vc]  @     0   (32768)
//   em_odd  [3][CHUNK][Vc]   @ 32768   (24576)  compact odd-state emissions
//   sh_emb  [3][CHUNK]       @ 57344   (96)     blank emission per row
//   sh_a255 [2][CHUNK]       @ 57440   (64)     alpha[255] history (skew link)
//   sh_lz   [6]              @ 57504   (24)
//   sh_pair [2]              @ 57528   (8)
//   sh_tg   int[256]         @ 57536   (1024)
constexpr int SMEM_BYTES = 58560;

// One block per batch. 3-stage skewed pipeline per iteration g:
//   warps 2-7 : gather em_odd + logsumexp for group g
//   warp 0    : Viterbi states 0..255 for group g-1 (publishes alpha[255]/step)
//   warp 1    : Viterbi states 256..512 for group g-2 (consumes alpha[255])
__global__ void __launch_bounds__(256, 1)
dp_kernel(const float* __restrict__ logits,
          const int* __restrict__ targets,
          const int* __restrict__ loglens,
          const int* __restrict__ tgtlens) {
    extern __shared__ char sm[];
    float(*ring)[Vc] = (float(*)[Vc])(sm);
    float(*em_odd)[CHUNK][Vc] = (float(*)[CHUNK][Vc])(sm + 32768);
    float(*sh_emb)[CHUNK] = (float(*)[CHUNK])(sm + 57344);
    float(*sh_a255)[CHUNK] = (float(*)[CHUNK])(sm + 57440);
    float* sh_lz = (float*)(sm + 57504);
    float* sh_pair = (float*)(sm + 57528);
    int* sh_tg = (int*)(sm + 57536);

    const int b = blockIdx.x;
    const int tid = threadIdx.x;
    const int w = tid >> 5, lane = tid & 31;
    const int len = loglens[b];
    const int ul = tgtlens[b];
    const int idxb = 2 * ul;       // last blank state
    const int idxl = 2 * ul - 1;   // last label state
    const int lenm1 = len - 1;
    const int NL = (len + 7) >> 3; // groups to process

    const float* base = logits + (size_t)b * Tc * Vc;

    sh_tg[tid] = targets[b * Uc + tid];
    if (tid < 2) sh_pair[tid] = NEGV;

    // prologue: prefetch chunks 0..PREF-1
    {
        const char* cb = (const char*)base;
#pragma unroll
        for (int c = 0; c < PREF; ++c) {
            unsigned d0 = (unsigned)__cvta_generic_to_shared((char*)ring + c * 8192 + tid * 16);
            CP_ASYNC_16(d0, cb + c * 8192 + tid * 16);
            CP_ASYNC_16(d0 + 4096, cb + c * 8192 + tid * 16 + 4096);
            CP_COMMIT();
        }
    }

    // ---- DP thread state ----
    float A0 = NEGV, A1 = NEGV, A2 = NEGV, A3 = NEGV;
    float A4 = NEGV, A5 = NEGV, A6 = NEGV, A7 = NEGV, A8 = NEGV;
    int e1 = 0, e3 = 0, e5 = 0, e7 = 0;
    bool k1 = false, k3 = false, k5 = false, k7 = false;
    float vb = NEGV, vl = NEGV;
    bool own_b = false, own_l = false, own_b8 = false;
    int ob = 0, ol = 0, u0 = 0;

    if (w < 2) {
        const int s0 = 256 * w + 8 * lane;
        u0 = s0 >> 1;  // 128w + 4*lane, int4-aligned
        const int* tg = targets + b * Uc;
        int4 t4 = *(const int4*)(tg + u0);
        e1 = t4.x; e3 = t4.y; e5 = t4.z; e7 = t4.w;
        k1 = (u0 > 0) && (e1 != tg[u0 - 1]);
        k3 = (e3 != e1); k5 = (e5 != e3); k7 = (e7 != e5);
        if (w == 0 && lane == 0) A0 = 0.f;  // virtual alpha_{-1}[0]=0
        if ((idxb >> 3) == (s0 >> 3)) { own_b = true; ob = idxb & 7; }
        if ((idxl >> 3) == (s0 >> 3)) { own_l = true; ol = idxl & 7; }
        if (idxb == 512 && w == 1 && lane == 31) own_b8 = true;
    }
    float accLZ = 0.f;

    int qh = 0, qw0 = 2, qw1 = 1;  // mod-3 tile buffer cursors

    for (int g = 0; g <= NL + 1; ++g) {
        if (g < NL) CP_WAIT(PREF - 1);
        __syncthreads();
        if (g < NL) {
            int c = g + PREF;
            if (c < NL) {
                const char* cb = (const char*)base + (size_t)c * 8192 + tid * 16;
                unsigned d0 = (unsigned)__cvta_generic_to_shared(
                    (char*)ring + (c & (NCH - 1)) * 8192 + tid * 16);
                CP_ASYNC_16(d0, cb);
                CP_ASYNC_16(d0 + 4096, cb + 4096);
            }
            CP_COMMIT();
        }

        if (w >= 2) {
            if (g < NL) {
                const int slot = (g & (NCH - 1)) * CHUNK;
                // gather compact emission tile: 64 (row, ublock) pairs over 6 warps
                for (int p = w - 2; p < 64; p += 6) {
                    int r = p >> 3, ub = p & 7;
                    int u = (ub << 5) + lane;
                    em_odd[qh][r][u] = ring[slot + r][sh_tg[u]];
                    if (ub == 0 && lane == 0) sh_emb[qh][r] = ring[slot + r][0];
                }
                // logsumexp of this group's rows
                for (int r = w - 2; r < 8; r += 6) {
                    int t = g * 8 + r;
                    if (t < len) {
                        const float4* r4 = (const float4*)ring[slot + r];
                        float4 x = r4[lane * 2], y = r4[lane * 2 + 1];
                        const float L2E = 1.4426950408889634f;
                        float s = exp2f(x.x * L2E) + exp2f(x.y * L2E) +
                                  exp2f(x.z * L2E) + exp2f(x.w * L2E) +
                                  exp2f(y.x * L2E) + exp2f(y.y * L2E) +
                                  exp2f(y.z * L2E) + exp2f(y.w * L2E);
#pragma unroll
                        for (int o = 16; o; o >>= 1) s += __shfl_xor_sync(0xffffffffu, s, o);
                        accLZ += 0.69314718055994531f * log2f(s);
                    }
                }
            }
        } else {
            const int gr = g - 1 - w;  // group this DP warp processes
            if (gr >= 0 && gr < NL) {
                const int q = w ? qw1 : qw0;
                const int pa = gr & 1;
                const int t0 = gr * 8;
                const float* emrow0 = &em_odd[q][0][u0];
#pragma unroll
                for (int r = 0; r < 8; ++r) {
                    float4 em4 = *(const float4*)(emrow0 + r * Vc);
                    float emb = sh_emb[q][r];
                    float P7 = __shfl_up_sync(0xffffffffu, A7, 1);
                    if (lane == 0) P7 = w ? sh_a255[pa][r] : NEGV;
                    float n0 = fmaxf(A0, P7) + emb;
                    float n1 = fmaxf(fmaxf(A1, A0), k1 ? P7 : NEGV) + em4.x;
                    float n2 = fmaxf(A2, A1) + emb;
                    float n3 = fmaxf(fmaxf(A3, A2), k3 ? A1 : NEGV) + em4.y;
                    float n4 = fmaxf(A4, A3) + emb;
                    float n5 = fmaxf(fmaxf(A5, A4), k5 ? A3 : NEGV) + em4.z;
                    float n6 = fmaxf(A6, A5) + emb;
                    float n7 = fmaxf(fmaxf(A7, A6), k7 ? A5 : NEGV) + em4.w;
                    if (w == 1) A8 = fmaxf(A8, A7) + emb;  // state 512 (lane31)
                    A0 = n0; A1 = n1; A2 = n2; A3 = n3;
                    A4 = n4; A5 = n5; A6 = n6; A7 = n7;
                    if (w == 0 && lane == 31) sh_a255[pa][r] = A7;  // alpha[255] at t0+r
                    int t = t0 + r;
                    if (t == lenm1) {
                        if (own_b) vb = (ob & 4) ? ((ob & 2) ? A6 : A4) : ((ob & 2) ? A2 : A0);
                        if (own_b8) vb = A8;
                        if (own_l) vl = (ol & 4) ? ((ol & 2) ? A7 : A5) : ((ol & 2) ? A3 : A1);
                    }
                }
            }
        }
        qh = (qh == 2) ? 0 : qh + 1;
        qw0 = (qw0 == 2) ? 0 : qw0 + 1;
        qw1 = (qw1 == 2) ? 0 : qw1 + 1;
    }

    __syncthreads();
    if (w >= 2 && lane == 0) sh_lz[w - 2] = accLZ;
    if (own_b || own_b8) sh_pair[0] = vb;
    if (own_l) sh_pair[1] = vl;
    __syncthreads();
    if (tid == 0) {
        float s = 0.f;
#pragma unroll
        for (int i = 0; i < 6; ++i) s += sh_lz[i];
        g_partial[b] = s - fmaxf(sh_pair[0], sh_pair[1]);
    }
}

// loss = sum_b partial[b] / sum_b len[b]   (fixed-order, deterministic)
__global__ void __launch_bounds__(32) finalize_kernel(const int* __restrict__ loglens,
                                                      float* __restrict__ out) {
    int lane = threadIdx.x;
    float num = g_partial[lane] + g_partial[lane + 32];
    float den = (float)loglens[lane] + (float)loglens[lane + 32];
#pragma unroll
    for (int o = 16; o; o >>= 1) {
        num += __shfl_down_sync(0xffffffffu, num, o);
        den += __shfl_down_sync(0xffffffffu, den, o);
    }
    if (lane == 0) out[0] = num / den;
}

extern "C" void kernel_launch(void* const* d_in, const int* in_sizes, int n_in,
                              void* d_out, int out_size) {
    const float* logits = (const float*)d_in[0];
    const int* targets = (const int*)d_in[1];
    const int* loglens = (const int*)d_in[2];
    const int* tgtlens = (const int*)d_in[3];
    float* out = (float*)d_out;

    static bool attr_set = false;
    if (!attr_set) {
        cudaFuncSetAttribute(dp_kernel, cudaFuncAttributeMaxDynamicSharedMemorySize,
                             SMEM_BYTES);
        attr_set = true;
    }

    dp_kernel<<<Bc, 256, SMEM_BYTES>>>(logits, targets, loglens, tgtlens);
    finalize_kernel<<<1, 32>>>(loglens, out);
}

// round 12
// speedup vs baseline: 1.4111x; 1.4111x over previous
#include <cuda_runtime.h>
#include <cuda_bf16.h>
#include <math.h>

// Shapes fixed by the reference
constexpr int Bc = 64;
constexpr int Tc = 2048;
constexpr int Vc = 256;
constexpr int Uc = 256;
#define NEGV (-1e30f)

constexpr int CHUNK = 8;   // timesteps per cp.async group (8 KB)
constexpr int NCH = 3;     // ring chunks (mod-3 cursor)
constexpr int PREF = 2;    // chunks in flight

__device__ float g_partial[Bc];

#define CP_ASYNC_16(dst, src)                                              \
    asm volatile("cp.async.cg.shared.global [%0], [%1], 16;\n" ::          \
                     "r"(dst), "l"(src))
#define CP_COMMIT() asm volatile("cp.async.commit_group;\n" ::: "memory")
#define CP_WAIT(n) asm volatile("cp.async.wait_group %0;\n" ::"n"(n) : "memory")

// One block per batch. 2-stage pipeline per iteration g:
//   warps 1-7 : gather em_tile[g&1] + logsumexp for group g (from cp.async ring)
//   warp 0    : Viterbi DP (all 513 states, 16 states/thread) for group g-1
// All shared memory static (42.2 KB < 48 KB): no dynamic-smem opt-in needed.
__global__ void __launch_bounds__(256, 1)
dp_kernel(const float* __restrict__ logits,
          const int* __restrict__ targets,
          const int* __restrict__ loglens,
          const int* __restrict__ tgtlens) {
    __shared__ float ring[NCH][CHUNK * Vc];     // 24576 B
    __shared__ float em_tile[2][CHUNK * Vc];    // 16384 B  pre-gathered odd emissions
    __shared__ float sh_emb[2][CHUNK];          // blank emission per row
    __shared__ int sh_tg[Uc];
    __shared__ float sh_dump[40];               // final-frame alpha snapshots (2x20)
    __shared__ float sh_lz[8];

    const int b = blockIdx.x;
    const int tid = threadIdx.x;
    const int w = tid >> 5, lane = tid & 31;
    const int len = loglens[b];
    const int ul = tgtlens[b];
    const int idxb = 2 * ul;        // last blank state (<= 512)
    const int idxl = 2 * ul - 1;    // last label state
    const int lenm1 = len - 1;
    const int NL = (len + 7) >> 3;

    const float* base = logits + (size_t)b * Tc * Vc;

    sh_tg[tid] = targets[b * Uc + tid];

    // prologue: prefetch chunks 0..PREF-1 into slots 0..PREF-1
    {
        const char* cb = (const char*)base;
#pragma unroll
        for (int c = 0; c < PREF; ++c) {
            unsigned d0 = (unsigned)__cvta_generic_to_shared((char*)ring[c] + tid * 16);
            CP_ASYNC_16(d0, cb + c * 8192 + tid * 16);
            CP_ASYNC_16(d0 + 4096, cb + c * 8192 + tid * 16 + 4096);
            CP_COMMIT();
        }
    }
    __syncthreads();  // sh_tg visible to helper preload below

    // ---- per-thread persistent state ----
    float A0 = NEGV, A1 = NEGV, A2 = NEGV, A3 = NEGV, A4 = NEGV, A5 = NEGV;
    float A6 = NEGV, A7 = NEGV, A8 = NEGV, A9 = NEGV, A10 = NEGV, A11 = NEGV;
    float A12 = NEGV, A13 = NEGV, A14 = NEGV, A15 = NEGV, A16 = NEGV;
    bool k0 = false, k1 = false, k2 = false, k3 = false;
    bool k4 = false, k5 = false, k6 = false, k7 = false;
    int lb = 0, ll = 0;            // snapshot owner lanes
    int tgv[10];                   // helper: gathered target ids (group-invariant)
    float accLZ = 0.f;

    if (w == 0) {
        // lane handles states 16*lane .. 16*lane+15 (+ state 512 on lane 31 = A16)
        const int u0 = 8 * lane;   // odd-state label indices u0..u0+7
        const int* tg = targets + b * Uc;
        int4 ta = *(const int4*)(tg + u0);
        int4 tb = *(const int4*)(tg + u0 + 4);
        int tprev = (u0 > 0) ? tg[u0 - 1] : 0;
        k0 = (u0 > 0) && (ta.x != tprev);   // state 16l+1 (s>=3 iff u0>0)
        k1 = (ta.y != ta.x);
        k2 = (ta.z != ta.y);
        k3 = (ta.w != ta.z);
        k4 = (tb.x != ta.w);
        k5 = (tb.y != tb.x);
        k6 = (tb.z != tb.y);
        k7 = (tb.w != tb.z);
        if (lane == 0) A0 = 0.f;   // virtual alpha_{-1}[0] = 0
        lb = (idxb >= 512) ? 31 : (idxb >> 4);
        ll = idxl >> 4;
    } else {
        // preload target values for my (r, ublock) gather pairs
#pragma unroll
        for (int i = 0; i < 10; ++i) {
            int p = (w - 1) + 7 * i;
            tgv[i] = (p < 64) ? sh_tg[((p & 7) << 5) + lane] : 0;
        }
    }

    int sl = 0;  // ring slot holding chunk g (mod-3 cursor)
    for (int g = 0; g <= NL; ++g) {
        if (g < NL) CP_WAIT(PREF - 1);
        __syncthreads();  // ring chunk g ready; em_tile[(g-1)&1] ready for DP
        if (g < NL) {
            int c = g + PREF;
            if (c < NL) {
                // slot of chunk c = (sl + PREF) % 3 = (sl - 1) mod 3
                int slc = sl - 1; if (slc < 0) slc += NCH;
                const char* cb = (const char*)base + (size_t)c * 8192 + tid * 16;
                unsigned d0 = (unsigned)__cvta_generic_to_shared((char*)ring[slc] + tid * 16);
                CP_ASYNC_16(d0, cb);
                CP_ASYNC_16(d0 + 4096, cb + 4096);
            }
            CP_COMMIT();  // keep per-thread group count uniform
        }

        if (w == 0) {
            if (g >= 1) {
                const int gr = g - 1;
                const float* tile = em_tile[gr & 1];
                const float* erow = sh_emb[gr & 1];
                const int t0 = gr * 8;
#pragma unroll
                for (int r = 0; r < 8; ++r) {
                    float4 lo = *(const float4*)(tile + r * Vc + 8 * lane);
                    float4 hi = *(const float4*)(tile + r * Vc + 8 * lane + 4);
                    float emb = erow[r];
                    float P = __shfl_up_sync(0xffffffffu, A15, 1);
                    if (lane == 0) P = NEGV;
                    float n0 = fmaxf(A0, P) + emb;
                    float n1 = fmaxf(fmaxf(A1, A0), k0 ? P : NEGV) + lo.x;
                    float n2 = fmaxf(A2, A1) + emb;
                    float n3 = fmaxf(fmaxf(A3, A2), k1 ? A1 : NEGV) + lo.y;
                    float n4 = fmaxf(A4, A3) + emb;
                    float n5 = fmaxf(fmaxf(A5, A4), k2 ? A3 : NEGV) + lo.z;
                    float n6 = fmaxf(A6, A5) + emb;
                    float n7 = fmaxf(fmaxf(A7, A6), k3 ? A5 : NEGV) + lo.w;
                    float n8 = fmaxf(A8, A7) + emb;
                    float n9 = fmaxf(fmaxf(A9, A8), k4 ? A7 : NEGV) + hi.x;
                    float n10 = fmaxf(A10, A9) + emb;
                    float n11 = fmaxf(fmaxf(A11, A10), k5 ? A9 : NEGV) + hi.y;
                    float n12 = fmaxf(A12, A11) + emb;
                    float n13 = fmaxf(fmaxf(A13, A12), k6 ? A11 : NEGV) + hi.z;
                    float n14 = fmaxf(A14, A13) + emb;
                    float n15 = fmaxf(fmaxf(A15, A14), k7 ? A13 : NEGV) + hi.w;
                    float n16 = fmaxf(A16, A15) + emb;  // state 512 (lane 31)
                    A0 = n0; A1 = n1; A2 = n2; A3 = n3; A4 = n4; A5 = n5;
                    A6 = n6; A7 = n7; A8 = n8; A9 = n9; A10 = n10; A11 = n11;
                    A12 = n12; A13 = n13; A14 = n14; A15 = n15; A16 = n16;
                    if (t0 + r == lenm1) {
                        if (lane == lb) {
                            float* d = sh_dump;
                            d[0] = A0; d[1] = A1; d[2] = A2; d[3] = A3;
                            d[4] = A4; d[5] = A5; d[6] = A6; d[7] = A7;
                            d[8] = A8; d[9] = A9; d[10] = A10; d[11] = A11;
                            d[12] = A12; d[13] = A13; d[14] = A14; d[15] = A15;
                            d[16] = A16;
                        }
                        if (lane == ll) {
                            float* d = sh_dump + 20;
                            d[0] = A0; d[1] = A1; d[2] = A2; d[3] = A3;
                            d[4] = A4; d[5] = A5; d[6] = A6; d[7] = A7;
                            d[8] = A8; d[9] = A9; d[10] = A10; d[11] = A11;
                            d[12] = A12; d[13] = A13; d[14] = A14; d[15] = A15;
                            d[16] = A16;
                        }
                    }
                }
            }
        } else if (g < NL) {
            const float* rslot = ring[sl];
            float* tile = em_tile[g & 1];
            // gather compact odd-emission tile: 64 (row, ublock) pairs over 7 warps
#pragma unroll
            for (int i = 0; i < 10; ++i) {
                int p = (w - 1) + 7 * i;
                if (p < 64) {
                    int r = p >> 3, ub = p & 7;
                    tile[r * Vc + (ub << 5) + lane] = rslot[r * Vc + tgv[i]];
                }
            }
            if (w == 1 && lane < 8) sh_emb[g & 1][lane] = rslot[lane * Vc];
            // logsumexp of this group's rows
            for (int r = w - 1; r < 8; r += 7) {
                int t = g * 8 + r;
                if (t < len) {
                    const float4* r4 = (const float4*)(rslot + r * Vc);
                    float4 x = r4[lane * 2], y = r4[lane * 2 + 1];
                    const float L2E = 1.4426950408889634f;
                    float s = exp2f(x.x * L2E) + exp2f(x.y * L2E) +
                              exp2f(x.z * L2E) + exp2f(x.w * L2E) +
                              exp2f(y.x * L2E) + exp2f(y.y * L2E) +
                              exp2f(y.z * L2E) + exp2f(y.w * L2E);
#pragma unroll
                    for (int o = 16; o; o >>= 1) s += __shfl_xor_sync(0xffffffffu, s, o);
                    accLZ += 0.69314718055994531f * log2f(s);
                }
            }
        }
        if (++sl == NCH) sl = 0;
    }

    __syncthreads();
    if (w >= 1 && lane == 0) sh_lz[w - 1] = accLZ;
    __syncthreads();
    if (tid == 0) {
        float s = 0.f;
#pragma unroll
        for (int i = 0; i < 7; ++i) s += sh_lz[i];
        const int ob = (idxb >= 512) ? 16 : (idxb & 15);
        const int ol = idxl & 15;
        float vb = sh_dump[ob];
        float vl = sh_dump[20 + ol];
        g_partial[b] = s - fmaxf(vb, vl);
    }
}

// loss = sum_b partial[b] / sum_b len[b]   (fixed-order, deterministic)
__global__ void __launch_bounds__(32) finalize_kernel(const int* __restrict__ loglens,
                                                      float* __restrict__ out) {
    int lane = threadIdx.x;
    float num = g_partial[lane] + g_partial[lane + 32];
    float den = (float)loglens[lane] + (float)loglens[lane + 32];
#pragma unroll
    for (int o = 16; o; o >>= 1) {
        num += __shfl_down_sync(0xffffffffu, num, o);
        den += __shfl_down_sync(0xffffffffu, den, o);
    }
    if (lane == 0) out[0] = num / den;
}

extern "C" void kernel_launch(void* const* d_in, const int* in_sizes, int n_in,
                              void* d_out, int out_size) {
    const float* logits = (const float*)d_in[0];
    const int* targets = (const int*)d_in[1];
    const int* loglens = (const int*)d_in[2];
    const int* tgtlens = (const int*)d_in[3];
    float* out = (float*)d_out;

    dp_kernel<<<Bc, 256>>>(logits, targets, loglens, tgtlens);
    finalize_kernel<<<1, 32>>>(loglens, out);
}

// round 13
// speedup vs baseline: 2.4051x; 1.7044x over previous
#include <cuda_runtime.h>
#include <cuda_bf16.h>
#include <math.h>

// Shapes fixed by the reference
constexpr int Bc = 64;
constexpr int Tc = 2048;
constexpr int Vc = 256;
constexpr int Uc = 256;
#define NEGV (-1e30f)

constexpr int CHUNK = 8;   // timesteps per cp.async group (8 KB)
constexpr int NCH = 3;     // ring chunks (mod-3 cursor)
constexpr int PREF = 2;    // chunks in flight

__device__ float g_partial[Bc];

#define CP_ASYNC_16(dst, src)                                              \
    asm volatile("cp.async.cg.shared.global [%0], [%1], 16;\n" ::          \
                     "r"(dst), "l"(src))
#define CP_COMMIT() asm volatile("cp.async.commit_group;\n" ::: "memory")
#define CP_WAIT(n) asm volatile("cp.async.wait_group %0;\n" ::"n"(n) : "memory")

// One block per batch. 2-stage pipeline per iteration g:
//   warps 4-7 : gather em_tile[g&1] + logsumexp for group g (from cp.async ring)
//   warps 0-3 : Viterbi DP for group g-1; warp w owns states [128w, 128w+128),
//               4 states/lane (+ state 512 on w3 lane31). Cross-warp coupling via
//               per-group 16-state halo snapshot (parity-buffered, barrier-ordered).
__global__ void __launch_bounds__(256, 1)
dp_kernel(const float* __restrict__ logits,
          const int* __restrict__ targets,
          const int* __restrict__ loglens,
          const int* __restrict__ tgtlens) {
    __shared__ float ring[NCH][CHUNK * Vc];     // 24576 B
    __shared__ float em_tile[2][CHUNK * Vc];    // 16384 B  pre-gathered odd emissions
    __shared__ float sh_emb[2][CHUNK];          // blank emission per row
    __shared__ int sh_tg[Uc];
    __shared__ float sh_halo[2][3][16];         // alpha[128(w+1)-16..-1] snapshots
    __shared__ float sh_all[516];               // final-frame alpha, all states
    __shared__ float sh_lz[4];

    const int b = blockIdx.x;
    const int tid = threadIdx.x;
    const int w = tid >> 5, lane = tid & 31;
    const int len = loglens[b];
    const int ul = tgtlens[b];
    const int idxb = 2 * ul;        // last blank state (<= 512)
    const int idxl = 2 * ul - 1;    // last label state
    const int lenm1 = len - 1;
    const int NL = (len + 7) >> 3;

    const float* base = logits + (size_t)b * Tc * Vc;

    sh_tg[tid] = targets[b * Uc + tid];
    if (tid < 96) ((float*)sh_halo)[tid] = NEGV;

    // prologue: prefetch chunks 0..PREF-1 into slots 0..PREF-1
    {
        const char* cb = (const char*)base;
#pragma unroll
        for (int c = 0; c < PREF; ++c) {
            unsigned d0 = (unsigned)__cvta_generic_to_shared((char*)ring[c] + tid * 16);
            CP_ASYNC_16(d0, cb + c * 8192 + tid * 16);
            CP_ASYNC_16(d0 + 4096, cb + c * 8192 + tid * 16 + 4096);
            CP_COMMIT();
        }
    }
    __syncthreads();  // sh_tg / sh_halo init visible

    // ---- per-thread persistent state ----
    float A0 = NEGV, A1 = NEGV, A2 = NEGV, A3 = NEGV, A4 = NEGV;
    bool k0 = false, k1 = false, kh = false;
    int u0 = 0, uh = 0, s0 = 0;
    int tgv[16];
    float accLZ = 0.f;

    if (w < 4) {
        // lane owns states s0..s0+3; odd labels at u0, u0+1
        s0 = 128 * w + 4 * lane;
        u0 = 64 * w + 2 * lane;
        const int* tg = targets + b * Uc;
        int ta = tg[u0], tb2 = tg[u0 + 1];
        k0 = (u0 >= 1) && (ta != tg[(u0 >= 1) ? u0 - 1 : 0]);
        k1 = (tb2 != ta);
        // halo metadata (w>0, lanes 0-7 meaningful): halo odd label u = 64w-8+j
        int j = (lane < 7) ? lane : 7;
        uh = (w > 0) ? (64 * w - 8 + j) : 0;
        kh = (w > 0) && (tg[uh] != tg[(uh >= 1) ? uh - 1 : 0]);
        if (w == 0 && lane == 0) A0 = 0.f;   // virtual alpha_{-1}[0] = 0
    } else {
        // helper: preload target ids for my 16 (row, ublock) gather pairs
#pragma unroll
        for (int i = 0; i < 16; ++i) {
            int p = (w - 4) + 4 * i;
            tgv[i] = sh_tg[((p & 7) << 5) + lane];
        }
    }

    int sl = 0;  // ring slot holding chunk g (mod-3 cursor)
    for (int g = 0; g <= NL; ++g) {
        if (g < NL) CP_WAIT(PREF - 1);
        __syncthreads();  // ring chunk g ready; em_tile[(g-1)&1] + halo[(g-1)&1] ready
        if (g < NL) {
            int c = g + PREF;
            if (c < NL) {
                int slc = sl - 1; if (slc < 0) slc += NCH;  // slot of chunk c
                const char* cb = (const char*)base + (size_t)c * 8192 + tid * 16;
                unsigned d0 = (unsigned)__cvta_generic_to_shared((char*)ring[slc] + tid * 16);
                CP_ASYNC_16(d0, cb);
                CP_ASYNC_16(d0 + 4096, cb + 4096);
            }
            CP_COMMIT();  // keep per-thread group count uniform
        }

        if (w < 4) {
            if (g >= 1) {
                const int gr = g - 1;
                const float* tile = em_tile[gr & 1];
                const float* erow = sh_emb[gr & 1];
                const int t0 = gr * 8;
                // load halo snapshot (alpha at t0-1 of states 128w-16..128w-1)
                float HE = NEGV, HO = NEGV;
                if (w > 0) {
                    int j2 = 2 * ((lane < 7) ? lane : 7);
                    HE = sh_halo[gr & 1][w - 1][j2];
                    HO = sh_halo[gr & 1][w - 1][j2 + 1];
                }
#pragma unroll
                for (int r = 0; r < 8; ++r) {
                    float2 e2 = *(const float2*)(tile + r * Vc + u0);
                    float eh = tile[r * Vc + uh];
                    float emb = erow[r];
                    float HOtop = __shfl_sync(0xffffffffu, HO, 7);  // alpha[128w-1] old
                    float P = __shfl_up_sync(0xffffffffu, A3, 1);   // alpha[s0-1] old
                    if (lane == 0) P = (w > 0) ? HOtop : NEGV;
                    // halo advance (meaningful lanes 0-7, w>0; harmless elsewhere)
                    float POh = __shfl_up_sync(0xffffffffu, HO, 1);
                    if (lane == 0) POh = NEGV;
                    float HEn = fmaxf(HE, POh) + emb;
                    float HOn = fmaxf(fmaxf(HO, HE), kh ? POh : NEGV) + eh;
                    HE = HEn; HO = HOn;
                    // main 4-state update
                    float n0 = fmaxf(A0, P) + emb;
                    float n1 = fmaxf(fmaxf(A1, A0), k0 ? P : NEGV) + e2.x;
                    float n2 = fmaxf(A2, A1) + emb;
                    float n3 = fmaxf(fmaxf(A3, A2), k1 ? A1 : NEGV) + e2.y;
                    if (w == 3) A4 = fmaxf(A4, A3) + emb;  // state 512 (lane 31)
                    A0 = n0; A1 = n1; A2 = n2; A3 = n3;
                    if (t0 + r == lenm1) {
                        *(float4*)(sh_all + s0) = make_float4(A0, A1, A2, A3);
                        if (w == 3 && lane == 31) sh_all[512] = A4;
                    }
                }
                // publish halo for next group (alpha at t0+7 of my top 16 states)
                if (w < 3 && lane >= 28) {
                    float* hdst = &sh_halo[g & 1][w][(lane - 28) * 4];
                    hdst[0] = A0; hdst[1] = A1; hdst[2] = A2; hdst[3] = A3;
                }
            }
        } else if (g < NL) {
            const float* rslot = ring[sl];
            float* tile = em_tile[g & 1];
            // gather compact odd-emission tile: 64 (row, ublock) pairs over 4 warps
#pragma unroll
            for (int i = 0; i < 16; ++i) {
                int p = (w - 4) + 4 * i;
                int r = p >> 3, ub = p & 7;
                tile[r * Vc + (ub << 5) + lane] = rslot[r * Vc + tgv[i]];
            }
            if (w == 4 && lane < 8) sh_emb[g & 1][lane] = rslot[lane * Vc];
            // logsumexp of this group's rows (2 rows per helper warp)
            for (int r = w - 4; r < 8; r += 4) {
                int t = g * 8 + r;
                if (t < len) {
                    const float4* r4 = (const float4*)(rslot + r * Vc);
                    float4 x = r4[lane * 2], y = r4[lane * 2 + 1];
                    const float L2E = 1.4426950408889634f;
                    float s = exp2f(x.x * L2E) + exp2f(x.y * L2E) +
                              exp2f(x.z * L2E) + exp2f(x.w * L2E) +
                              exp2f(y.x * L2E) + exp2f(y.y * L2E) +
                              exp2f(y.z * L2E) + exp2f(y.w * L2E);
#pragma unroll
                    for (int o = 16; o; o >>= 1) s += __shfl_xor_sync(0xffffffffu, s, o);
                    accLZ += 0.69314718055994531f * log2f(s);
                }
            }
        }
        if (++sl == NCH) sl = 0;
    }

    __syncthreads();
    if (w >= 4 && lane == 0) sh_lz[w - 4] = accLZ;
    __syncthreads();
    if (tid == 0) {
        float s = sh_lz[0] + sh_lz[1] + sh_lz[2] + sh_lz[3];
        g_partial[b] = s - fmaxf(sh_all[idxb], sh_all[idxl]);
    }
}

// loss = sum_b partial[b] / sum_b len[b]   (fixed-order, deterministic)
__global__ void __launch_bounds__(32) finalize_kernel(const int* __restrict__ loglens,
                                                      float* __restrict__ out) {
    int lane = threadIdx.x;
    float num = g_partial[lane] + g_partial[lane + 32];
    float den = (float)loglens[lane] + (float)loglens[lane + 32];
#pragma unroll
    for (int o = 16; o; o >>= 1) {
        num += __shfl_down_sync(0xffffffffu, num, o);
        den += __shfl_down_sync(0xffffffffu, den, o);
    }
    if (lane == 0) out[0] = num / den;
}

extern "C" void kernel_launch(void* const* d_in, const int* in_sizes, int n_in,
                              void* d_out, int out_size) {
    const float* logits = (const float*)d_in[0];
    const int* targets = (const int*)d_in[1];
    const int* loglens = (const int*)d_in[2];
    const int* tgtlens = (const int*)d_in[3];
    float* out = (float*)d_out;

    dp_kernel<<<Bc, 256>>>(logits, targets, loglens, tgtlens);
    finalize_kernel<<<1, 32>>>(loglens, out);
}

// round 15
// speedup vs baseline: 3.3549x; 1.3949x over previous
#include <cuda_runtime.h>
#include <cuda_bf16.h>
#include <math.h>

// Shapes fixed by the reference
constexpr int Bc = 64;
constexpr int Tc = 2048;
constexpr int Vc = 256;
constexpr int Uc = 256;
#define NEGV (-1e30f)

constexpr int CHUNK = 8;   // timesteps per cp.async group (8 KB)
constexpr int NCH = 3;     // ring chunks (mod-3 cursor)
constexpr int PREF = 2;    // chunks in flight

constexpr int LZ_BLOCKS = 512;     // extra blocks doing logsumexp
constexpr int LZ_ROWS = (Bc * Tc) / LZ_BLOCKS;  // 32 rows per block

__device__ float g_logZ[Bc * Tc];
__device__ float g_score[Bc];      // -viterbi_score per batch

#define CP_ASYNC_16(dst, src)                                              \
    asm volatile("cp.async.cg.shared.global [%0], [%1], 16;\n" ::          \
                     "r"(dst), "l"(src))
#define CP_COMMIT() asm volatile("cp.async.commit_group;\n" ::: "memory")
#define CP_WAIT(n) asm volatile("cp.async.wait_group %0;\n" ::"n"(n) : "memory")

// Blocks 0..63: one per batch. 2-stage pipeline per iteration g:
//   warps 4-7 : gather em_tile[g&1] for group g (from cp.async ring)  [no lse]
//   warps 0-3 : Viterbi DP for group g-1; warp w owns states [128w,128w+128),
//               4 states/lane (+ state 512 on w3 lane31). All emissions preloaded
//               to registers per group; 2 shuffles/step; 16-state halo recompute
//               on lanes 24-31, cross-warp link via per-group parity snapshot.
// Blocks 64..575: logsumexp, warp-per-row, 32 rows each -> g_logZ.
__global__ void __launch_bounds__(256, 1)
dp_kernel(const float* __restrict__ logits,
          const int* __restrict__ targets,
          const int* __restrict__ loglens,
          const int* __restrict__ tgtlens) {
    const int bid = blockIdx.x;
    const int tid = threadIdx.x;
    const int w = tid >> 5, lane = tid & 31;

    if (bid >= Bc) {
        // ---------------- logsumexp blocks ----------------
        const int r0 = (bid - Bc) * LZ_ROWS;
        const float L2E = 1.4426950408889634f;
        for (int rr = w; rr < LZ_ROWS; rr += 8) {
            const float4* r4 = (const float4*)(logits + (size_t)(r0 + rr) * Vc);
            float4 x = r4[lane];
            float4 y = r4[lane + 32];
            float s = exp2f(x.x * L2E) + exp2f(x.y * L2E) +
                      exp2f(x.z * L2E) + exp2f(x.w * L2E) +
                      exp2f(y.x * L2E) + exp2f(y.y * L2E) +
                      exp2f(y.z * L2E) + exp2f(y.w * L2E);
#pragma unroll
            for (int o = 16; o; o >>= 1) s += __shfl_xor_sync(0xffffffffu, s, o);
            if (lane == 0) g_logZ[r0 + rr] = 0.69314718055994531f * log2f(s);
        }
        return;
    }

    // ---------------- DP blocks ----------------
    __shared__ float ring[NCH][CHUNK * Vc];     // 24576 B
    __shared__ float em_tile[2][CHUNK * Vc];    // 16384 B  pre-gathered odd emissions
    __shared__ float sh_emb[2][CHUNK];          // blank emission per row
    __shared__ int sh_tg[Uc];
    __shared__ float sh_halo[2][3][16];         // top-16 alpha snapshots (parity)
    __shared__ float sh_all[516];               // final-frame alpha, all states

    const int b = bid;
    const int len = loglens[b];
    const int ul = tgtlens[b];
    const int idxb = 2 * ul;        // last blank state (<= 512)
    const int idxl = 2 * ul - 1;    // last label state
    const int lenm1 = len - 1;
    const int NL = (len + 7) >> 3;

    const float* base = logits + (size_t)b * Tc * Vc;

    sh_tg[tid] = targets[b * Uc + tid];
    if (tid < 96) ((float*)sh_halo)[tid] = NEGV;

    // prologue: prefetch chunks 0..PREF-1 into slots 0..PREF-1
    {
        const char* cb = (const char*)base;
#pragma unroll
        for (int c = 0; c < PREF; ++c) {
            unsigned d0 = (unsigned)__cvta_generic_to_shared((char*)ring[c] + tid * 16);
            CP_ASYNC_16(d0, cb + c * 8192 + tid * 16);
            CP_ASYNC_16(d0 + 4096, cb + c * 8192 + tid * 16 + 4096);
            CP_COMMIT();
        }
    }
    __syncthreads();  // sh_tg / sh_halo init visible

    // ---- per-thread persistent state ----
    float A0 = NEGV, A1 = NEGV, A2 = NEGV, A3 = NEGV, A4 = NEGV;
    float HE = NEGV, HO = NEGV;
    bool k0 = false, k1 = false, kh = false;
    int u0 = 0, uh = 0, s0 = 0;
    int tgv[16];

    if (w < 4) {
        // lane owns states s0..s0+3; odd labels at u0, u0+1
        s0 = 128 * w + 4 * lane;
        u0 = 64 * w + 2 * lane;
        const int* tg = targets + b * Uc;
        int ta = tg[u0], tb2 = tg[u0 + 1];
        k0 = (u0 >= 1) && (ta != tg[(u0 >= 1) ? u0 - 1 : 0]);
        k1 = (tb2 != ta);
        // halo on lanes 24-31: j = lane-24, odd label u = 64w-8+j
        int j = lane - 24; if (j < 0) j = 0;
        uh = (w > 0) ? (64 * w - 8 + j) : 0;
        kh = (w > 0) && (tg[uh] != tg[(uh >= 1) ? uh - 1 : 0]);
        if (w == 0 && lane == 0) A0 = 0.f;   // virtual alpha_{-1}[0] = 0
    } else {
        // helper: preload target ids for my 16 (row, ublock) gather pairs
#pragma unroll
        for (int i = 0; i < 16; ++i) {
            int p = (w - 4) + 4 * i;
            tgv[i] = sh_tg[((p & 7) << 5) + lane];
        }
    }

    int sl = 0;  // ring slot holding chunk g (mod-3 cursor)
    for (int g = 0; g <= NL; ++g) {
        if (g < NL) CP_WAIT(PREF - 1);
        __syncthreads();  // ring chunk g ready; em_tile[(g-1)&1] + halo[(g-1)&1] ready
        if (g < NL) {
            int c = g + PREF;
            if (c < NL) {
                int slc = sl - 1; if (slc < 0) slc += NCH;  // slot of chunk c
                const char* cb = (const char*)base + (size_t)c * 8192 + tid * 16;
                unsigned d0 = (unsigned)__cvta_generic_to_shared((char*)ring[slc] + tid * 16);
                CP_ASYNC_16(d0, cb);
                CP_ASYNC_16(d0 + 4096, cb + 4096);
            }
            CP_COMMIT();  // keep per-thread group count uniform
        }

        if (w < 4) {
            if (g >= 1) {
                const int gr = g - 1;
                const float* tile = em_tile[gr & 1];
                const int t0 = gr * 8;
                // ---- bulk-load this group's emissions into registers ----
                float2 E2[8];
                float EH[8], EB[8];
#pragma unroll
                for (int r = 0; r < 8; ++r) {
                    E2[r] = *(const float2*)(tile + r * Vc + u0);
                    EH[r] = tile[r * Vc + uh];
                    EB[r] = sh_emb[gr & 1][r];
                }
                // halo snapshot (alpha at t0-1 of states 128w-16..128w-1), lanes 24-31
                if (w > 0) {
                    int j = lane - 24; if (j < 0) j = 0;
                    HE = sh_halo[gr & 1][w - 1][2 * j];
                    HO = sh_halo[gr & 1][w - 1][2 * j + 1];
                }
#pragma unroll
                for (int r = 0; r < 8; ++r) {
                    // P: alpha[s0-1] old; lane0 <- old HO of lane31 (state 128w-1)
                    float v = (lane == 31) ? HO : A3;
                    float P = __shfl_sync(0xffffffffu, v, (lane + 31) & 31);
                    if (w == 0 && lane == 0) P = NEGV;
                    // halo advance (lanes 24-31 meaningful, uses old HE/HO)
                    float POh = __shfl_up_sync(0xffffffffu, HO, 1);
                    if (lane == 24) POh = NEGV;
                    float HEn = fmaxf(HE, POh) + EB[r];
                    float HOn = fmaxf(fmaxf(HO, HE), kh ? POh : NEGV) + EH[r];
                    // main 4-state update (old A's)
                    float n0 = fmaxf(A0, P) + EB[r];
                    float n1 = fmaxf(fmaxf(A1, A0), k0 ? P : NEGV) + E2[r].x;
                    float n2 = fmaxf(A2, A1) + EB[r];
                    float n3 = fmaxf(fmaxf(A3, A2), k1 ? A1 : NEGV) + E2[r].y;
                    if (w == 3) A4 = fmaxf(A4, A3) + EB[r];  // state 512 (lane 31)
                    A0 = n0; A1 = n1; A2 = n2; A3 = n3;
                    HE = HEn; HO = HOn;
                    if (t0 + r == lenm1) {
                        *(float4*)(sh_all + s0) = make_float4(A0, A1, A2, A3);
                        if (w == 3 && lane == 31) sh_all[512] = A4;
                    }
                }
                // publish halo for next group (alpha at t0+7 of my top 16 states)
                if (w < 3 && lane >= 28) {
                    float* hdst = &sh_halo[g & 1][w][(lane - 28) * 4];
                    hdst[0] = A0; hdst[1] = A1; hdst[2] = A2; hdst[3] = A3;
                }
            }
        } else if (g < NL) {
            const float* rslot = ring[sl];
            float* tile = em_tile[g & 1];
            // gather compact odd-emission tile: 64 (row, ublock) pairs over 4 warps
#pragma unroll
            for (int i = 0; i < 16; ++i) {
                int p = (w - 4) + 4 * i;
                int r = p >> 3, ub = p & 7;
                tile[r * Vc + (ub << 5) + lane] = rslot[r * Vc + tgv[i]];
            }
            if (w == 4 && lane < 8) sh_emb[g & 1][lane] = rslot[lane * Vc];
        }
        if (++sl == NCH) sl = 0;
    }

    __syncthreads();
    if (tid == 0) g_score[b] = -fmaxf(sh_all[idxb], sh_all[idxl]);
}

// loss = sum_b ( sum_{t<len_b} logZ[b,t] + g_score[b] ) / sum_b len_b
// Fixed-order, deterministic.
__global__ void __launch_bounds__(1024) finalize_kernel(const int* __restrict__ loglens,
                                                        float* __restrict__ out) {
    __shared__ float partial[Bc];
    int w = threadIdx.x >> 5;
    int lane = threadIdx.x & 31;
    for (int b = w; b < Bc; b += 32) {
        int len = loglens[b];
        float acc = 0.f;
        for (int t = lane; t < Tc; t += 32) {
            if (t < len) acc += g_logZ[b * Tc + t];
        }
#pragma unroll
        for (int o = 16; o; o >>= 1) acc += __shfl_down_sync(0xffffffffu, acc, o);
        if (lane == 0) partial[b] = acc + g_score[b];
    }
    __syncthreads();
    if (threadIdx.x == 0) {
        float num = 0.f, den = 0.f;
        for (int b = 0; b < Bc; ++b) {
            num += partial[b];
            den += (float)loglens[b];
        }
        out[0] = num / den;
    }
}

extern "C" void kernel_launch(void* const* d_in, const int* in_sizes, int n_in,
                              void* d_out, int out_size) {
    const float* logits = (const float*)d_in[0];
    const int* targets = (const int*)d_in[1];
    const int* loglens = (const int*)d_in[2];
    const int* tgtlens = (const int*)d_in[3];
    float* out = (float*)d_out;

    dp_kernel<<<Bc + LZ_BLOCKS, 256>>>(logits, targets, loglens, tgtlens);
    finalize_kernel<<<1, 1024>>>(loglens, out);
}